// round 4
// baseline (speedup 1.0000x reference)
#include <cuda_runtime.h>
#include <cuda_bf16.h>

#define VDIM 128
#define NUM_EMB (VDIM * VDIM * VDIM)
#define TPB 320                // 64 slots per block, 5 threads per slot
#define NBUCKET 128
#define REP 8                  // sub-bins per z-bucket (spreads atomics, keeps z order)
#define NBINS (NBUCKET * REP)  // 1024
#define CAP 1152               // slots per bin slab (mean ~976 at n=1e6)
#define NSLOTS (NBINS * CAP)   // 1,179,648
#define SPILL_CAP 65536
#define TOTAL_SLOTS (NSLOTS + SPILL_CAP)   // 1,245,184 (divisible by 64)
#define MAXN (1 << 20)

__device__ int    d_cnt[NBINS];
__device__ int    d_spill_cnt;
__device__ float4 d_xs[TOTAL_SLOTS];   // [bin*CAP + pos] then spill region; w = bitcast(p)

__device__ __forceinline__ int zbucket(float pz) {
    int b = (int)floorf((pz + 1.0f) * 64.0f);
    return min(max(b, 0), NBUCKET - 1);
}

__global__ void zero_cnt_kernel() {
    int t = blockIdx.x * blockDim.x + threadIdx.x;
    if (t < NBINS) d_cnt[t] = 0;
    if (t == NBINS) d_spill_cnt = 0;
}

// 8 points per thread: coalesced float4 input, batched atomics (MLP=8), batched stores.
__global__ __launch_bounds__(256) void scatter_kernel(const float* __restrict__ x, int n) {
    int t = blockIdx.x * blockDim.x + threadIdx.x;
    int p0 = t * 8;
    if (p0 >= n) return;

    float px[8], py[8], pz[8];
    if (p0 + 8 <= n) {
        const float4* __restrict__ x4 = (const float4*)(x + p0 * 3);
        float4 a = __ldg(x4 + 0), b = __ldg(x4 + 1), c = __ldg(x4 + 2);
        float4 d = __ldg(x4 + 3), e = __ldg(x4 + 4), f = __ldg(x4 + 5);
        px[0]=a.x; py[0]=a.y; pz[0]=a.z;
        px[1]=a.w; py[1]=b.x; pz[1]=b.y;
        px[2]=b.z; py[2]=b.w; pz[2]=c.x;
        px[3]=c.y; py[3]=c.z; pz[3]=c.w;
        px[4]=d.x; py[4]=d.y; pz[4]=d.z;
        px[5]=d.w; py[5]=e.x; pz[5]=e.y;
        px[6]=e.z; py[6]=e.w; pz[6]=f.x;
        px[7]=f.y; py[7]=f.z; pz[7]=f.w;
    } else {
        for (int i = 0; i < 8; i++) {
            int p = p0 + i;
            if (p < n) {
                px[i] = __ldg(x + 3*p + 0);
                py[i] = __ldg(x + 3*p + 1);
                pz[i] = __ldg(x + 3*p + 2);
            } else {
                px[i] = py[i] = pz[i] = 0.0f;
            }
        }
    }

    int bin[8], pos[8];
#pragma unroll
    for (int i = 0; i < 8; i++)
        bin[i] = zbucket(pz[i]) * REP + i;       // rep = i: lanes of one unroll step spread bins
#pragma unroll
    for (int i = 0; i < 8; i++) {
        if (p0 + i < n) pos[i] = atomicAdd(&d_cnt[bin[i]], 1);
    }
#pragma unroll
    for (int i = 0; i < 8; i++) {
        int p = p0 + i;
        if (p >= n) continue;
        float4 rec = make_float4(px[i], py[i], pz[i], __int_as_float(p));
        if (pos[i] < CAP) {
            d_xs[bin[i] * CAP + pos[i]] = rec;
        } else {
            int sp = atomicAdd(&d_spill_cnt, 1);
            if (sp < SPILL_CAP) d_xs[NSLOTS + sp] = rec;
            // (spill overflow impossible: SPILL_CAP=64K vs statistical overflow of a few)
        }
    }
}

template <bool PERMUTED>
__global__ __launch_bounds__(TPB) void dense_grid_interp_kernel(
    const float* __restrict__ x,     // used only when !PERMUTED
    const float* __restrict__ grid,  // [NUM_EMB, 20]
    float* __restrict__ out,         // [n, 20]
    int n)
{
    int t = blockIdx.x * TPB + threadIdx.x;
    int ps = t / 5;       // slot index
    int c = t - ps * 5;   // which float4 of the 20 channels

    int p;
    float px, py, pz;
    if (PERMUTED) {
        if (ps < NSLOTS) {
            int bin = ps / CAP;
            int idx = ps - bin * CAP;
            int cnt = min(__ldg(&d_cnt[bin]), CAP);
            if (idx >= cnt) return;
        } else {
            if (ps >= TOTAL_SLOTS) return;
            int idx = ps - NSLOTS;
            if (idx >= min(__ldg(&d_spill_cnt), SPILL_CAP)) return;
        }
        float4 xp = __ldg(&d_xs[ps]);            // coalesced sorted read
        px = xp.x; py = xp.y; pz = xp.z;
        p = __float_as_int(xp.w);
    } else {
        if (ps >= n) return;
        p = ps;
        px = __ldg(x + 3 * p + 0);
        py = __ldg(x + 3 * p + 1);
        pz = __ldg(x + 3 * p + 2);
    }

    // (x - lo)/len * V  ==  (x+1)*64  (exact in fp32)
    float fx = (px + 1.0f) * 64.0f;
    float fy = (py + 1.0f) * 64.0f;
    float fz = (pz + 1.0f) * 64.0f;

    float gx = floorf(fx), gy = floorf(fy), gz = floorf(fz);
    float wx1 = fx - gx, wy1 = fy - gy, wz1 = fz - gz;
    float wx0 = 1.0f - wx1, wy0 = 1.0f - wy1, wz0 = 1.0f - wz1;

    int ix = (int)gx, iy = (int)gy, iz = (int)gz;
    int base = ix + (iy << 7) + (iz << 14);

    int f0 = base;
    int f1 = base + 1;
    int f2 = base + VDIM;
    int f3 = base + VDIM + 1;
    int f4 = base + VDIM * VDIM;
    int f5 = f4 + 1;
    int f6 = f4 + VDIM;
    int f7 = f6 + 1;

    // JAX gather clamps out-of-bounds flat indices (gp+1 can reach 128)
    const int last = NUM_EMB - 1;
    f0 = min(f0, last); f1 = min(f1, last); f2 = min(f2, last); f3 = min(f3, last);
    f4 = min(f4, last); f5 = min(f5, last); f6 = min(f6, last); f7 = min(f7, last);

    const float4* __restrict__ g4 = (const float4*)grid;
    float4 q0 = __ldg(g4 + f0 * 5 + c);
    float4 q1 = __ldg(g4 + f1 * 5 + c);
    float4 q2 = __ldg(g4 + f2 * 5 + c);
    float4 q3 = __ldg(g4 + f3 * 5 + c);
    float4 q4 = __ldg(g4 + f4 * 5 + c);
    float4 q5 = __ldg(g4 + f5 * 5 + c);
    float4 q6 = __ldg(g4 + f6 * 5 + c);
    float4 q7 = __ldg(g4 + f7 * 5 + c);

    float w0 = wx0 * wy0 * wz0;
    float w1 = wx1 * wy0 * wz0;
    float w2 = wx0 * wy1 * wz0;
    float w3 = wx1 * wy1 * wz0;
    float w4 = wx0 * wy0 * wz1;
    float w5 = wx1 * wy0 * wz1;
    float w6 = wx0 * wy1 * wz1;
    float w7 = wx1 * wy1 * wz1;

    float4 r;
    r.x = w0*q0.x + w1*q1.x + w2*q2.x + w3*q3.x + w4*q4.x + w5*q5.x + w6*q6.x + w7*q7.x;
    r.y = w0*q0.y + w1*q1.y + w2*q2.y + w3*q3.y + w4*q4.y + w5*q5.y + w6*q6.y + w7*q7.y;
    r.z = w0*q0.z + w1*q1.z + w2*q2.z + w3*q3.z + w4*q4.z + w5*q5.z + w6*q6.z + w7*q7.z;
    r.w = w0*q0.w + w1*q1.w + w2*q2.w + w3*q3.w + w4*q4.w + w5*q5.w + w6*q6.w + w7*q7.w;

    ((float4*)out)[p * 5 + c] = r;
}

extern "C" void kernel_launch(void* const* d_in, const int* in_sizes, int n_in,
                              void* d_out, int out_size) {
    const float* x    = (const float*)d_in[0];   // [n, 3] float32
    const float* grid = (const float*)d_in[1];   // [NUM_EMB, 20] float32
    float* out = (float*)d_out;                  // [n, 20] float32

    int n = in_sizes[0] / 3;

    if (n > MAXN) {
        long long th = (long long)n * 5;
        int blocks = (int)((th + TPB - 1) / TPB);
        dense_grid_interp_kernel<false><<<blocks, TPB>>>(x, grid, out, n);
        return;
    }

    zero_cnt_kernel<<<(NBINS + 256) / 256, 256>>>();
    int sthreads = (n + 7) / 8;
    scatter_kernel<<<(sthreads + 255) / 256, 256>>>(x, n);
    long long th = (long long)TOTAL_SLOTS * 5;
    int blocks = (int)((th + TPB - 1) / TPB);
    dense_grid_interp_kernel<true><<<blocks, TPB>>>(x, grid, out, n);
}

// round 6
// speedup vs baseline: 1.6209x; 1.6209x over previous
#include <cuda_runtime.h>
#include <cuda_bf16.h>
#include <cstdint>

#define VDIM 128
#define NUM_EMB (VDIM * VDIM * VDIM)
#define TPB 320   // 64 points per point, 5 threads per point

// Create an L2 "evict_last" cache policy descriptor (fraction = 1.0).
__device__ __forceinline__ uint64_t mk_policy_evict_last() {
    uint64_t pol;
    asm volatile("createpolicy.fractional.L2::evict_last.b64 %0, 1.0;" : "=l"(pol));
    return pol;
}

// Grid gather: non-coherent load with evict_last cache hint.
__device__ __forceinline__ float4 ldg_grid(const float4* p, uint64_t pol) {
    float4 v;
    asm volatile("ld.global.nc.L2::cache_hint.v4.f32 {%0,%1,%2,%3}, [%4], %5;"
                 : "=f"(v.x), "=f"(v.y), "=f"(v.z), "=f"(v.w)
                 : "l"(p), "l"(pol));
    return v;
}

// Output: streaming store (evict-first, don't pollute L2)
__device__ __forceinline__ void stg_out(float4* p, float4 v) {
    asm volatile("st.global.cs.v4.f32 [%0], {%1,%2,%3,%4};"
                 :: "l"(p), "f"(v.x), "f"(v.y), "f"(v.z), "f"(v.w)
                 : "memory");
}

__global__ __launch_bounds__(TPB) void dense_grid_interp_kernel(
    const float* __restrict__ x,     // [n, 3]
    const float* __restrict__ grid,  // [NUM_EMB, 20]
    float* __restrict__ out,         // [n, 20]
    int n)
{
    int t = blockIdx.x * TPB + threadIdx.x;
    int p = t / 5;        // point index
    int c = t - p * 5;    // which float4 of the 20 channels
    if (p >= n) return;

    uint64_t pol = mk_policy_evict_last();

    float px = __ldg(x + 3 * p + 0);
    float py = __ldg(x + 3 * p + 1);
    float pz = __ldg(x + 3 * p + 2);

    // (x - lo)/len * V  ==  (x+1)*64  (exact in fp32)
    float fx = (px + 1.0f) * 64.0f;
    float fy = (py + 1.0f) * 64.0f;
    float fz = (pz + 1.0f) * 64.0f;

    float gx = floorf(fx), gy = floorf(fy), gz = floorf(fz);
    float wx1 = fx - gx, wy1 = fy - gy, wz1 = fz - gz;
    float wx0 = 1.0f - wx1, wy0 = 1.0f - wy1, wz0 = 1.0f - wz1;

    int ix = (int)gx, iy = (int)gy, iz = (int)gz;
    int base = ix + (iy << 7) + (iz << 14);

    int f0 = base;
    int f1 = base + 1;
    int f2 = base + VDIM;
    int f3 = base + VDIM + 1;
    int f4 = base + VDIM * VDIM;
    int f5 = f4 + 1;
    int f6 = f4 + VDIM;
    int f7 = f6 + 1;

    // JAX gather clamps out-of-bounds flat indices (gp+1 can reach 128)
    const int last = NUM_EMB - 1;
    f0 = min(f0, last); f1 = min(f1, last); f2 = min(f2, last); f3 = min(f3, last);
    f4 = min(f4, last); f5 = min(f5, last); f6 = min(f6, last); f7 = min(f7, last);

    const float4* __restrict__ g4 = (const float4*)grid;
    float4 q0 = ldg_grid(g4 + f0 * 5 + c, pol);
    float4 q1 = ldg_grid(g4 + f1 * 5 + c, pol);
    float4 q2 = ldg_grid(g4 + f2 * 5 + c, pol);
    float4 q3 = ldg_grid(g4 + f3 * 5 + c, pol);
    float4 q4 = ldg_grid(g4 + f4 * 5 + c, pol);
    float4 q5 = ldg_grid(g4 + f5 * 5 + c, pol);
    float4 q6 = ldg_grid(g4 + f6 * 5 + c, pol);
    float4 q7 = ldg_grid(g4 + f7 * 5 + c, pol);

    float w0 = wx0 * wy0 * wz0;
    float w1 = wx1 * wy0 * wz0;
    float w2 = wx0 * wy1 * wz0;
    float w3 = wx1 * wy1 * wz0;
    float w4 = wx0 * wy0 * wz1;
    float w5 = wx1 * wy0 * wz1;
    float w6 = wx0 * wy1 * wz1;
    float w7 = wx1 * wy1 * wz1;

    float4 r;
    r.x = w0*q0.x + w1*q1.x + w2*q2.x + w3*q3.x + w4*q4.x + w5*q5.x + w6*q6.x + w7*q7.x;
    r.y = w0*q0.y + w1*q1.y + w2*q2.y + w3*q3.y + w4*q4.y + w5*q5.y + w6*q6.y + w7*q7.y;
    r.z = w0*q0.z + w1*q1.z + w2*q2.z + w3*q3.z + w4*q4.z + w5*q5.z + w6*q6.z + w7*q7.z;
    r.w = w0*q0.w + w1*q1.w + w2*q2.w + w3*q3.w + w4*q4.w + w5*q5.w + w6*q6.w + w7*q7.w;

    stg_out((float4*)out + p * 5 + c, r);
}

extern "C" void kernel_launch(void* const* d_in, const int* in_sizes, int n_in,
                              void* d_out, int out_size) {
    const float* x    = (const float*)d_in[0];   // [n, 3] float32
    const float* grid = (const float*)d_in[1];   // [NUM_EMB, 20] float32
    float* out = (float*)d_out;                  // [n, 20] float32

    int n = in_sizes[0] / 3;
    long long total_threads = (long long)n * 5;
    int blocks = (int)((total_threads + TPB - 1) / TPB);
    dense_grid_interp_kernel<<<blocks, TPB>>>(x, grid, out, n);
}